// round 6
// baseline (speedup 1.0000x reference)
#include <cuda_runtime.h>
#include <cuda_bf16.h>
#include <cstdint>

#define NB 8
#define NS 1024
#define ND 1024
#define NH 16
#define NDH 64
#define KAUG 3072   // augmented K for QKV GEMM: [hi, hi/lo, lo/hi]

// ---------------- scratch (static device globals) ----------------
__device__ float g_rowsum[NB * NH * NS];
__device__ __align__(128) __nv_bfloat16 g_A[(size_t)NB * NS * KAUG];   // [xh|xh|xl]
__device__ __align__(128) __nv_bfloat16 g_Bm[3 * (size_t)ND * KAUG];   // [wh|wl|wh]
// attention operands, bf16 splits, seg-major: [bh][seg][s][64]
__device__ __align__(128) __nv_bfloat16 g_Qs[(size_t)NB * NH * 3 * NS * NDH]; // [qh|qh|ql]*0.125
__device__ __align__(128) __nv_bfloat16 g_Ks[(size_t)NB * NH * 3 * NS * NDH]; // [kh|kl|kh]
__device__ __align__(128) __nv_bfloat16 g_Vs[(size_t)NB * NH * 2 * NS * NDH]; // [vh|vl]

// ---------------- PTX helpers (compute_103-safe) ----------------
__device__ __forceinline__ uint32_t smem_u32(const void* p) {
    uint32_t a;
    asm("{ .reg .u64 t; cvta.to.shared.u64 t, %1; cvt.u32.u64 %0, t; }" : "=r"(a) : "l"(p));
    return a;
}
__device__ __forceinline__ void cp_async16(uint32_t dst, const void* src) {
    asm volatile("cp.async.cg.shared.global [%0], [%1], 16;" :: "r"(dst), "l"(src));
}
#define CP_COMMIT() asm volatile("cp.async.commit_group;" ::: "memory")
#define CP_WAIT(n)  asm volatile("cp.async.wait_group %0;" :: "n"(n) : "memory")

__device__ __forceinline__ void ldsm4(uint32_t* r, uint32_t addr) {
    asm volatile("ldmatrix.sync.aligned.m8n8.x4.shared.b16 {%0,%1,%2,%3}, [%4];"
                 : "=r"(r[0]), "=r"(r[1]), "=r"(r[2]), "=r"(r[3]) : "r"(addr));
}
__device__ __forceinline__ void ldsm4t(uint32_t* r, uint32_t addr) {
    asm volatile("ldmatrix.sync.aligned.m8n8.x4.trans.shared.b16 {%0,%1,%2,%3}, [%4];"
                 : "=r"(r[0]), "=r"(r[1]), "=r"(r[2]), "=r"(r[3]) : "r"(addr));
}
__device__ __forceinline__ void mma16816(float* c, const uint32_t* a, const uint32_t* b) {
    asm volatile("mma.sync.aligned.m16n8k16.row.col.f32.bf16.bf16.f32 "
                 "{%0,%1,%2,%3}, {%4,%5,%6,%7}, {%8,%9}, {%0,%1,%2,%3};"
                 : "+f"(c[0]), "+f"(c[1]), "+f"(c[2]), "+f"(c[3])
                 : "r"(a[0]), "r"(a[1]), "r"(a[2]), "r"(a[3]), "r"(b[0]), "r"(b[1]));
}
__device__ __forceinline__ void mma16816v(float* c, const uint32_t* a, uint32_t b0, uint32_t b1) {
    asm volatile("mma.sync.aligned.m16n8k16.row.col.f32.bf16.bf16.f32 "
                 "{%0,%1,%2,%3}, {%4,%5,%6,%7}, {%8,%9}, {%0,%1,%2,%3};"
                 : "+f"(c[0]), "+f"(c[1]), "+f"(c[2]), "+f"(c[3])
                 : "r"(a[0]), "r"(a[1]), "r"(a[2]), "r"(a[3]), "r"(b0), "r"(b1));
}
__device__ __forceinline__ uint32_t sw128(uint32_t off) { return off ^ ((off >> 3) & 0x70); }

// ============================================================================
// Prep: split fp32 -> bf16 hi/lo, build augmented K-major operands for QKV.
// ============================================================================
__global__ __launch_bounds__(256) void prep_x_kernel(const float* __restrict__ x)
{
    size_t e = ((size_t)blockIdx.x * 256 + threadIdx.x) * 4;
    int m = (int)(e >> 10), k = (int)(e & 1023);
    float4 v = *(const float4*)&x[e];
    __nv_bfloat162 h01 = __floats2bfloat162_rn(v.x, v.y);
    __nv_bfloat162 h23 = __floats2bfloat162_rn(v.z, v.w);
    __nv_bfloat162 l01 = __floats2bfloat162_rn(v.x - __bfloat162float(h01.x),
                                               v.y - __bfloat162float(h01.y));
    __nv_bfloat162 l23 = __floats2bfloat162_rn(v.z - __bfloat162float(h23.x),
                                               v.w - __bfloat162float(h23.y));
    size_t ro = (size_t)m * KAUG;
    *(__nv_bfloat162*)&g_A[ro + k]            = h01;
    *(__nv_bfloat162*)&g_A[ro + k + 2]        = h23;
    *(__nv_bfloat162*)&g_A[ro + 1024 + k]     = h01;
    *(__nv_bfloat162*)&g_A[ro + 1024 + k + 2] = h23;
    *(__nv_bfloat162*)&g_A[ro + 2048 + k]     = l01;
    *(__nv_bfloat162*)&g_A[ro + 2048 + k + 2] = l23;
}

__global__ __launch_bounds__(256) void prep_w_kernel(
    const float* __restrict__ Wq, const float* __restrict__ Wk, const float* __restrict__ Wv)
{
    int z = blockIdx.y;
    const float* W = (z == 0) ? Wq : (z == 1) ? Wk : Wv;
    __nv_bfloat16* gb = g_Bm + (size_t)z * ND * KAUG;
    size_t e = ((size_t)blockIdx.x * 256 + threadIdx.x) * 4;
    int n = (int)(e >> 10), k = (int)(e & 1023);
    float4 v = *(const float4*)&W[e];
    __nv_bfloat162 h01 = __floats2bfloat162_rn(v.x, v.y);
    __nv_bfloat162 h23 = __floats2bfloat162_rn(v.z, v.w);
    __nv_bfloat162 l01 = __floats2bfloat162_rn(v.x - __bfloat162float(h01.x),
                                               v.y - __bfloat162float(h01.y));
    __nv_bfloat162 l23 = __floats2bfloat162_rn(v.z - __bfloat162float(h23.x),
                                               v.w - __bfloat162float(h23.y));
    size_t ro = (size_t)n * KAUG;
    *(__nv_bfloat162*)&gb[ro + k]            = h01;
    *(__nv_bfloat162*)&gb[ro + k + 2]        = h23;
    *(__nv_bfloat162*)&gb[ro + 1024 + k]     = l01;
    *(__nv_bfloat162*)&gb[ro + 1024 + k + 2] = l23;
    *(__nv_bfloat162*)&gb[ro + 2048 + k]     = h01;
    *(__nv_bfloat162*)&gb[ro + 2048 + k + 2] = h23;
}

// ============================================================================
// QKV GEMM: CTA 256x256, 512 threads (16 warps, 4m x 4n, warp 64x64),
// K-tile 64, double buffer. grid (12 = 3z x 4n, 32 m).
// Epilogue writes bf16 hi/lo splits for the attention kernel.
// ============================================================================
#define QSTAGE 65536              // A 32KB + B 32KB
#define QKV_SMEM (2 * QSTAGE)

__global__ __launch_bounds__(512, 1)
void qkv_mma_kernel(const float* __restrict__ bq, const float* __restrict__ bk,
                    const float* __restrict__ bv)
{
    extern __shared__ char smraw[];
    __shared__ float biasS[256];
    uint32_t sm = smem_u32(smraw);

    int t = threadIdx.x;
    int wid = t >> 5, lane = t & 31;
    int warp_m = wid & 3, warp_n = wid >> 2;

    int bx = blockIdx.x;
    int z = bx >> 2;
    int n0 = (bx & 3) * 256;
    int m0 = blockIdx.y * 256;

    const float* bias = (z == 0) ? bq : (z == 1) ? bk : bv;
    const __nv_bfloat16* Asrc = g_A + (size_t)m0 * KAUG;
    const __nv_bfloat16* Bsrc = g_Bm + (size_t)z * ND * KAUG + (size_t)n0 * KAUG;

    if (t < 256) biasS[t] = bias[n0 + t];

    auto load_tile = [&](int kt, int s) {
        uint32_t base = sm + s * QSTAGE;
        int k0 = kt * 64;
        #pragma unroll
        for (int i = 0; i < 8; i++) {
            int c = t + i * 512;               // 0..4095 chunks of 16B
            int row = c >> 3, col = c & 7;
            uint32_t off = sw128((uint32_t)((row & 255) * 128 + col * 16));
            const __nv_bfloat16* src = (row < 256)
                ? Asrc + (size_t)row * KAUG + k0 + col * 8
                : Bsrc + (size_t)(row - 256) * KAUG + k0 + col * 8;
            cp_async16(base + (row < 256 ? 0u : 32768u) + off, src);
        }
    };

    float acc[4][8][4];
    #pragma unroll
    for (int mt = 0; mt < 4; mt++)
        #pragma unroll
        for (int nt = 0; nt < 8; nt++)
            #pragma unroll
            for (int r = 0; r < 4; r++) acc[mt][nt][r] = 0.f;

    uint32_t a_row = (uint32_t)(warp_m * 64 + (lane & 15));
    uint32_t a_kb  = (uint32_t)((lane >> 4) << 4);
    uint32_t b_row = (uint32_t)(warp_n * 64 + (lane & 15));

    load_tile(0, 0); CP_COMMIT();

    for (int kt = 0; kt < 48; kt++) {
        int cur = kt & 1;
        if (kt + 1 < 48) { load_tile(kt + 1, cur ^ 1); CP_COMMIT(); CP_WAIT(1); }
        else             { CP_WAIT(0); }
        __syncthreads();

        uint32_t abase = sm + cur * QSTAGE;
        uint32_t bbase = abase + 32768u;
        #pragma unroll
        for (int ks = 0; ks < 4; ks++) {
            uint32_t kb = (uint32_t)(ks * 32);
            uint32_t af[4][4], bw[4][4];
            #pragma unroll
            for (int mt = 0; mt < 4; mt++)
                ldsm4(af[mt], abase + sw128((a_row + mt * 16) * 128 + kb + a_kb));
            #pragma unroll
            for (int p = 0; p < 4; p++)
                ldsm4(bw[p], bbase + sw128((b_row + p * 16) * 128 + kb + a_kb));
            #pragma unroll
            for (int mt = 0; mt < 4; mt++)
                #pragma unroll
                for (int p = 0; p < 4; p++) {
                    mma16816v(acc[mt][2 * p],     af[mt], bw[p][0], bw[p][2]);
                    mma16816v(acc[mt][2 * p + 1], af[mt], bw[p][1], bw[p][3]);
                }
        }
        __syncthreads();
    }

    // ---- epilogue: bias (+0.125 scale for Q) -> bf16 hi/lo splits ----
    int gq = lane >> 2;
    float scale = (z == 0) ? 0.125f : 1.0f;
    #pragma unroll
    for (int mt = 0; mt < 4; mt++) {
        int m_lo = m0 + warp_m * 64 + mt * 16 + gq;
        #pragma unroll
        for (int half = 0; half < 2; half++) {
            int m = m_lo + half * 8;
            int b = m >> 10, s = m & 1023;
            #pragma unroll
            for (int nt = 0; nt < 8; nt++) {
                int nc = warp_n * 64 + nt * 8 + (lane & 3) * 2;
                int n = n0 + nc;
                int h = n >> 6, dh = n & 63;
                int bh = b * NH + h;
                float c0 = (acc[mt][nt][half * 2 + 0] + biasS[nc]) * scale;
                float c1 = (acc[mt][nt][half * 2 + 1] + biasS[nc + 1]) * scale;
                __nv_bfloat162 hv = __floats2bfloat162_rn(c0, c1);
                __nv_bfloat162 lv = __floats2bfloat162_rn(c0 - __bfloat162float(hv.x),
                                                          c1 - __bfloat162float(hv.y));
                if (z == 2) {
                    size_t o = (((size_t)bh * 2 + 0) * NS + s) * NDH + dh;
                    *(__nv_bfloat162*)&g_Vs[o] = hv;
                    *(__nv_bfloat162*)&g_Vs[o + (size_t)NS * NDH] = lv;
                } else {
                    __nv_bfloat16* dst = (z == 0) ? g_Qs : g_Ks;
                    size_t o = (((size_t)bh * 3 + 0) * NS + s) * NDH + dh;
                    size_t seg = (size_t)NS * NDH;
                    if (z == 0) {   // [qh|qh|ql]
                        *(__nv_bfloat162*)&dst[o]           = hv;
                        *(__nv_bfloat162*)&dst[o + seg]     = hv;
                        *(__nv_bfloat162*)&dst[o + 2 * seg] = lv;
                    } else {        // [kh|kl|kh]
                        *(__nv_bfloat162*)&dst[o]           = hv;
                        *(__nv_bfloat162*)&dst[o + seg]     = lv;
                        *(__nv_bfloat162*)&dst[o + 2 * seg] = hv;
                    }
                }
            }
        }
    }
}

// ============================================================================
// Attention via mma.sync. CTA: 64 q x one (b,h); 16 k-tiles of 64.
// smem 104KB -> 2 CTAs/SM. K' double-buffered, V single-buffered.
// ============================================================================
#define QS_OFF 0u            // 3 segs x 64 x 128B = 24576
#define KS_OFF 24576u        // 2 bufs x 24576 = 49152
#define VS_OFF 73728u        // 2 x 64 x 128B = 16384 (single buffer)
#define P_OFF  90112u        // Ph 8192 + Pl 8192
#define RS_OFF 106496u       // 64 floats
#define ATT_SMEM 106752u

__global__ __launch_bounds__(256, 2)
void attn_mma_kernel(float* __restrict__ out_ctx, float* __restrict__ out_att)
{
    extern __shared__ char smraw[];
    uint32_t sm = smem_u32(smraw);
    float* rowsumS = (float*)(smraw + RS_OFF);

    int t = threadIdx.x;
    int wid = t >> 5, lane = t & 31;
    int warp_m = wid & 1, warp_n = wid >> 1;
    int bh = blockIdx.y;
    int q0 = blockIdx.x * 64;

    const __nv_bfloat16* Qg = g_Qs + ((size_t)bh * 3 * NS + q0) * NDH;
    const __nv_bfloat16* Kg = g_Ks + (size_t)bh * 3 * NS * NDH;
    const __nv_bfloat16* Vg = g_Vs + (size_t)bh * 2 * NS * NDH;

    auto load_k = [&](int kt, int buf) {
        #pragma unroll
        for (int i = 0; i < 6; i++) {      // 1536 chunks
            int c = t + i * 256;
            int seg = c >> 9, row = (c >> 3) & 63, col = c & 7;
            cp_async16(sm + KS_OFF + buf * 24576u + seg * 8192u
                          + sw128((uint32_t)(row * 128 + col * 16)),
                       Kg + (((size_t)seg * NS) + kt * 64 + row) * NDH + col * 8);
        }
    };
    auto load_v = [&](int kt) {
        #pragma unroll
        for (int i = 0; i < 4; i++) {      // 1024 chunks
            int c = t + i * 256;
            int hl = c >> 9, row = (c >> 3) & 63, col = c & 7;
            cp_async16(sm + VS_OFF + hl * 8192u
                          + sw128((uint32_t)(row * 128 + col * 16)),
                       Vg + (((size_t)hl * NS) + kt * 64 + row) * NDH + col * 8);
        }
    };

    // prologue: Q (resident) + K(0) + V(0)
    #pragma unroll
    for (int i = 0; i < 6; i++) {
        int c = t + i * 256;
        int seg = c >> 9, row = (c >> 3) & 63, col = c & 7;
        cp_async16(sm + QS_OFF + seg * 8192u + sw128((uint32_t)(row * 128 + col * 16)),
                   Qg + ((size_t)seg * NS + row) * NDH + col * 8);
    }
    load_k(0, 0);
    load_v(0);
    CP_COMMIT();
    if (t < 64) rowsumS[t] = 0.f;

    float ctx[2][2][4];
    #pragma unroll
    for (int mt = 0; mt < 2; mt++)
        #pragma unroll
        for (int nt = 0; nt < 2; nt++)
            #pragma unroll
            for (int r = 0; r < 4; r++) ctx[mt][nt][r] = 0.f;

    uint32_t a_row = (uint32_t)(warp_m * 32 + (lane & 15));
    uint32_t a_kb  = (uint32_t)((lane >> 4) << 4);
    uint32_t b_row = (uint32_t)(warp_n * 16 + (lane & 15));

    for (int kt = 0; kt < 16; kt++) {
        int cur = kt & 1;
        CP_WAIT(0);
        __syncthreads();
        if (kt + 1 < 16) { load_k(kt + 1, cur ^ 1); CP_COMMIT(); }

        // ---- QK: M64 x N64 x K192 ----
        float sacc[2][2][4];
        #pragma unroll
        for (int mt = 0; mt < 2; mt++)
            #pragma unroll
            for (int nt = 0; nt < 2; nt++)
                #pragma unroll
                for (int r = 0; r < 4; r++) sacc[mt][nt][r] = 0.f;

        uint32_t kbase = sm + KS_OFF + cur * 24576u;
        #pragma unroll
        for (int ks = 0; ks < 12; ks++) {
            uint32_t seg = (uint32_t)(ks >> 2), kb = (uint32_t)((ks & 3) * 32);
            uint32_t af[2][4], bw[4];
            #pragma unroll
            for (int mt = 0; mt < 2; mt++)
                ldsm4(af[mt], sm + QS_OFF + seg * 8192u
                              + sw128((a_row + mt * 16) * 128 + kb + a_kb));
            ldsm4(bw, kbase + seg * 8192u + sw128(b_row * 128 + kb + a_kb));
            #pragma unroll
            for (int mt = 0; mt < 2; mt++) {
                mma16816v(sacc[mt][0], af[mt], bw[0], bw[2]);
                mma16816v(sacc[mt][1], af[mt], bw[1], bw[3]);
            }
        }

        // ---- exp, att out, rowsum, P split to smem ----
        size_t attbase = ((size_t)bh * NS + q0) * NS + (size_t)kt * 64;
        #pragma unroll
        for (int mt = 0; mt < 2; mt++) {
            float p0 = 0.f, p1 = 0.f;
            int r0 = warp_m * 32 + mt * 16 + (lane >> 2);
            #pragma unroll
            for (int nt = 0; nt < 2; nt++) {
                int kc = warp_n * 16 + nt * 8 + (lane & 3) * 2;
                float e0 = __expf(sacc[mt][nt][0]);
                float e1 = __expf(sacc[mt][nt][1]);
                float e2 = __expf(sacc[mt][nt][2]);
                float e3 = __expf(sacc[mt][nt][3]);
                p0 += e0 + e1; p1 += e2 + e3;
                *(float2*)&out_att[attbase + (size_t)r0 * NS + kc]       = make_float2(e0, e1);
                *(float2*)&out_att[attbase + (size_t)(r0 + 8) * NS + kc] = make_float2(e2, e3);
                __nv_bfloat162 h0 = __floats2bfloat162_rn(e0, e1);
                __nv_bfloat162 l0 = __floats2bfloat162_rn(e0 - __bfloat162float(h0.x),
                                                          e1 - __bfloat162float(h0.y));
                __nv_bfloat162 h1 = __floats2bfloat162_rn(e2, e3);
                __nv_bfloat162 l1 = __floats2bfloat162_rn(e2 - __bfloat162float(h1.x),
                                                          e3 - __bfloat162float(h1.y));
                uint32_t po  = sw128((uint32_t)(r0 * 128 + kc * 2));
                uint32_t po8 = sw128((uint32_t)((r0 + 8) * 128 + kc * 2));
                *(__nv_bfloat162*)(smraw + P_OFF + po)           = h0;
                *(__nv_bfloat162*)(smraw + P_OFF + 8192u + po)   = l0;
                *(__nv_bfloat162*)(smraw + P_OFF + po8)          = h1;
                *(__nv_bfloat162*)(smraw + P_OFF + 8192u + po8)  = l1;
            }
            p0 += __shfl_xor_sync(0xffffffffu, p0, 1);
            p0 += __shfl_xor_sync(0xffffffffu, p0, 2);
            p1 += __shfl_xor_sync(0xffffffffu, p1, 1);
            p1 += __shfl_xor_sync(0xffffffffu, p1, 2);
            if ((lane & 3) == 0) {
                atomicAdd(&rowsumS[r0], p0);
                atomicAdd(&rowsumS[r0 + 8], p1);
            }
        }
        __syncthreads();   // P complete; V(kt) also resident

        // ---- AV: 3 split terms, M64 x N64 x K64 ----
        #pragma unroll
        for (int term = 0; term < 3; term++) {
            uint32_t pb = sm + P_OFF + (term == 2 ? 8192u : 0u);
            uint32_t vb = sm + VS_OFF + (term == 1 ? 8192u : 0u);
            #pragma unroll
            for (int ks = 0; ks < 4; ks++) {
                uint32_t kbyte = (uint32_t)(ks * 32) + a_kb;   // 0..127
                uint32_t af[2][4], bv[4];
                #pragma unroll
                for (int mt = 0; mt < 2; mt++)
                    ldsm4(af[mt], pb + sw128((a_row + mt * 16) * 128 + kbyte));
                ldsm4t(bv, vb + sw128((uint32_t)((ks * 16 + (lane & 15)) * 128)
                                      + (uint32_t)(warp_n * 32) + (uint32_t)((lane >> 4) * 16)));
                #pragma unroll
                for (int mt = 0; mt < 2; mt++) {
                    mma16816(ctx[mt][0], af[mt], bv);
                    mma16816(ctx[mt][1], af[mt], bv + 2);
                }
            }
        }
        __syncthreads();   // V consumers done -> safe to overwrite
        if (kt + 1 < 16) { load_v(kt + 1); CP_COMMIT(); }
    }

    if (t < 64) g_rowsum[(size_t)bh * NS + q0 + t] = rowsumS[t];
    __syncthreads();

    // ---- normalized context write: [B,S,D] ----
    int b = bh >> 4, h = bh & 15;
    #pragma unroll
    for (int mt = 0; mt < 2; mt++) {
        #pragma unroll
        for (int half = 0; half < 2; half++) {
            int r = warp_m * 32 + mt * 16 + (lane >> 2) + half * 8;
            float inv = 1.0f / rowsumS[r];
            size_t o = ((size_t)(b * NS + q0 + r)) * ND + h * NDH;
            #pragma unroll
            for (int nt = 0; nt < 2; nt++) {
                int d = warp_n * 16 + nt * 8 + (lane & 3) * 2;
                float c0 = ctx[mt][nt][half * 2 + 0] * inv;
                float c1 = ctx[mt][nt][half * 2 + 1] * inv;
                *(float2*)&out_ctx[o + d] = make_float2(c0, c1);
            }
        }
    }
}

// ============================================================================
// Normalize attention tensor by row sums (pure HBM pass).
// ============================================================================
__global__ __launch_bounds__(256) void norm_kernel(float* __restrict__ att)
{
    size_t i = ((size_t)blockIdx.x * 256 + threadIdx.x) * 4;
    float inv = 1.0f / __ldg(&g_rowsum[i >> 10]);
    float4 v = *(float4*)&att[i];
    v.x *= inv; v.y *= inv; v.z *= inv; v.w *= inv;
    *(float4*)&att[i] = v;
}

extern "C" void kernel_launch(void* const* d_in, const int* in_sizes, int n_in,
                              void* d_out, int out_size) {
    const float* x  = (const float*)d_in[0];
    const float* Wq = (const float*)d_in[1];
    const float* bq = (const float*)d_in[2];
    const float* Wk = (const float*)d_in[3];
    const float* bk = (const float*)d_in[4];
    const float* Wv = (const float*)d_in[5];
    const float* bv = (const float*)d_in[6];
    // d_in[7] structure_bias: constant along the softmax axis -> cancels exactly.

    float* out_ctx = (float*)d_out;
    float* out_att = out_ctx + (size_t)NB * NS * ND;

    cudaFuncSetAttribute(qkv_mma_kernel, cudaFuncAttributeMaxDynamicSharedMemorySize, QKV_SMEM);
    cudaFuncSetAttribute(attn_mma_kernel, cudaFuncAttributeMaxDynamicSharedMemorySize, ATT_SMEM);

    prep_x_kernel<<<8192, 256>>>(x);
    prep_w_kernel<<<dim3(1024, 3), 256>>>(Wq, Wk, Wv);
    qkv_mma_kernel<<<dim3(12, 32), 512, QKV_SMEM>>>(bq, bk, bv);
    attn_mma_kernel<<<dim3(16, 128), 256, ATT_SMEM>>>(out_ctx, out_att);
    norm_kernel<<<131072, 256>>>(out_att);
}

// round 7
// speedup vs baseline: 1.9554x; 1.9554x over previous
#include <cuda_runtime.h>
#include <cuda_bf16.h>
#include <cstdint>

#define NB 8
#define NS 1024
#define ND 1024
#define NH 16
#define NDH 64
#define KAUG 3072   // augmented K for QKV GEMM: [hi, hi/lo, lo/hi]

// ---------------- scratch (static device globals) ----------------
__device__ float g_rowsum[NB * NH * NS];
__device__ __align__(128) __nv_bfloat16 g_A[(size_t)NB * NS * KAUG];   // [xh|xh|xl]
__device__ __align__(128) __nv_bfloat16 g_Bm[3 * (size_t)ND * KAUG];   // [wh|wl|wh]
// attention operands, bf16 splits, seg-major: [bh][seg][s][64]
__device__ __align__(128) __nv_bfloat16 g_Qs[(size_t)NB * NH * 3 * NS * NDH]; // [qh|qh|ql]*0.125
__device__ __align__(128) __nv_bfloat16 g_Ks[(size_t)NB * NH * 3 * NS * NDH]; // [kh|kl|kh]
__device__ __align__(128) __nv_bfloat16 g_Vs[(size_t)NB * NH * 2 * NS * NDH]; // [vh|vl]

// ---------------- PTX helpers (compute_103-safe) ----------------
__device__ __forceinline__ uint32_t smem_u32(const void* p) {
    uint32_t a;
    asm("{ .reg .u64 t; cvta.to.shared.u64 t, %1; cvt.u32.u64 %0, t; }" : "=r"(a) : "l"(p));
    return a;
}
__device__ __forceinline__ void cp_async16(uint32_t dst, const void* src) {
    asm volatile("cp.async.cg.shared.global [%0], [%1], 16;" :: "r"(dst), "l"(src));
}
#define CP_COMMIT() asm volatile("cp.async.commit_group;" ::: "memory")
#define CP_WAIT(n)  asm volatile("cp.async.wait_group %0;" :: "n"(n) : "memory")

__device__ __forceinline__ void ldsm4(uint32_t* r, uint32_t addr) {
    asm volatile("ldmatrix.sync.aligned.m8n8.x4.shared.b16 {%0,%1,%2,%3}, [%4];"
                 : "=r"(r[0]), "=r"(r[1]), "=r"(r[2]), "=r"(r[3]) : "r"(addr));
}
__device__ __forceinline__ void ldsm2(uint32_t* r, uint32_t addr) {
    asm volatile("ldmatrix.sync.aligned.m8n8.x2.shared.b16 {%0,%1}, [%2];"
                 : "=r"(r[0]), "=r"(r[1]) : "r"(addr));
}
__device__ __forceinline__ void ldsm4t(uint32_t* r, uint32_t addr) {
    asm volatile("ldmatrix.sync.aligned.m8n8.x4.trans.shared.b16 {%0,%1,%2,%3}, [%4];"
                 : "=r"(r[0]), "=r"(r[1]), "=r"(r[2]), "=r"(r[3]) : "r"(addr));
}
__device__ __forceinline__ void mma16816(float* c, const uint32_t* a, const uint32_t* b) {
    asm volatile("mma.sync.aligned.m16n8k16.row.col.f32.bf16.bf16.f32 "
                 "{%0,%1,%2,%3}, {%4,%5,%6,%7}, {%8,%9}, {%0,%1,%2,%3};"
                 : "+f"(c[0]), "+f"(c[1]), "+f"(c[2]), "+f"(c[3])
                 : "r"(a[0]), "r"(a[1]), "r"(a[2]), "r"(a[3]), "r"(b[0]), "r"(b[1]));
}
__device__ __forceinline__ void mma16816v(float* c, const uint32_t* a, uint32_t b0, uint32_t b1) {
    asm volatile("mma.sync.aligned.m16n8k16.row.col.f32.bf16.bf16.f32 "
                 "{%0,%1,%2,%3}, {%4,%5,%6,%7}, {%8,%9}, {%0,%1,%2,%3};"
                 : "+f"(c[0]), "+f"(c[1]), "+f"(c[2]), "+f"(c[3])
                 : "r"(a[0]), "r"(a[1]), "r"(a[2]), "r"(a[3]), "r"(b0), "r"(b1));
}
__device__ __forceinline__ uint32_t sw128(uint32_t off) { return off ^ ((off >> 3) & 0x70); }

// ============================================================================
// Prep: split fp32 -> bf16 hi/lo, build augmented K-major operands for QKV.
// ============================================================================
__global__ __launch_bounds__(256) void prep_x_kernel(const float* __restrict__ x)
{
    size_t e = ((size_t)blockIdx.x * 256 + threadIdx.x) * 4;
    int m = (int)(e >> 10), k = (int)(e & 1023);
    float4 v = *(const float4*)&x[e];
    __nv_bfloat162 h01 = __floats2bfloat162_rn(v.x, v.y);
    __nv_bfloat162 h23 = __floats2bfloat162_rn(v.z, v.w);
    __nv_bfloat162 l01 = __floats2bfloat162_rn(v.x - __bfloat162float(h01.x),
                                               v.y - __bfloat162float(h01.y));
    __nv_bfloat162 l23 = __floats2bfloat162_rn(v.z - __bfloat162float(h23.x),
                                               v.w - __bfloat162float(h23.y));
    size_t ro = (size_t)m * KAUG;
    *(__nv_bfloat162*)&g_A[ro + k]            = h01;
    *(__nv_bfloat162*)&g_A[ro + k + 2]        = h23;
    *(__nv_bfloat162*)&g_A[ro + 1024 + k]     = h01;
    *(__nv_bfloat162*)&g_A[ro + 1024 + k + 2] = h23;
    *(__nv_bfloat162*)&g_A[ro + 2048 + k]     = l01;
    *(__nv_bfloat162*)&g_A[ro + 2048 + k + 2] = l23;
}

__global__ __launch_bounds__(256) void prep_w_kernel(
    const float* __restrict__ Wq, const float* __restrict__ Wk, const float* __restrict__ Wv)
{
    int z = blockIdx.y;
    const float* W = (z == 0) ? Wq : (z == 1) ? Wk : Wv;
    __nv_bfloat16* gb = g_Bm + (size_t)z * ND * KAUG;
    size_t e = ((size_t)blockIdx.x * 256 + threadIdx.x) * 4;
    int n = (int)(e >> 10), k = (int)(e & 1023);
    float4 v = *(const float4*)&W[e];
    __nv_bfloat162 h01 = __floats2bfloat162_rn(v.x, v.y);
    __nv_bfloat162 h23 = __floats2bfloat162_rn(v.z, v.w);
    __nv_bfloat162 l01 = __floats2bfloat162_rn(v.x - __bfloat162float(h01.x),
                                               v.y - __bfloat162float(h01.y));
    __nv_bfloat162 l23 = __floats2bfloat162_rn(v.z - __bfloat162float(h23.x),
                                               v.w - __bfloat162float(h23.y));
    size_t ro = (size_t)n * KAUG;
    *(__nv_bfloat162*)&gb[ro + k]            = h01;
    *(__nv_bfloat162*)&gb[ro + k + 2]        = h23;
    *(__nv_bfloat162*)&gb[ro + 1024 + k]     = l01;
    *(__nv_bfloat162*)&gb[ro + 1024 + k + 2] = l23;
    *(__nv_bfloat162*)&gb[ro + 2048 + k]     = h01;
    *(__nv_bfloat162*)&gb[ro + 2048 + k + 2] = h23;
}

// ============================================================================
// QKV GEMM via mma.sync bf16. CTA 128x128, K-tile 64, double buffer.
// 2 CTAs/SM (66.5KB smem each) to raise tensor-pipe utilization.
// ============================================================================
#define STAGE_BYTES 32768
#define QKV_SMEM (2 * STAGE_BYTES + 1024)

__global__ __launch_bounds__(256, 2)
void qkv_mma_kernel(const float* __restrict__ bq, const float* __restrict__ bk,
                    const float* __restrict__ bv)
{
    extern __shared__ char smraw[];
    __shared__ float biasS[128];
    uint32_t sm = smem_u32(smraw);

    int t = threadIdx.x;
    int wid = t >> 5, lane = t & 31;
    int warp_m = wid & 1, warp_n = wid >> 1;

    int bx = blockIdx.x;
    int z = bx >> 3;
    int n0 = (bx & 7) * 128;
    int m0 = blockIdx.y * 128;

    const float* bias = (z == 0) ? bq : (z == 1) ? bk : bv;
    const __nv_bfloat16* Asrc = g_A + (size_t)m0 * KAUG;
    const __nv_bfloat16* Bsrc = g_Bm + (size_t)z * ND * KAUG + (size_t)n0 * KAUG;

    if (t < 128) biasS[t] = bias[n0 + t];

    auto load_tile = [&](int kt, int s) {
        uint32_t base = sm + s * STAGE_BYTES;
        int k0 = kt * 64;
        #pragma unroll
        for (int i = 0; i < 8; i++) {
            int c = t + i * 256;
            int row = c >> 3, col = c & 7;
            uint32_t off = sw128((uint32_t)((row & 127) * 128 + col * 16));
            const __nv_bfloat16* src = (row < 128)
                ? Asrc + (size_t)row * KAUG + k0 + col * 8
                : Bsrc + (size_t)(row - 128) * KAUG + k0 + col * 8;
            cp_async16(base + (row < 128 ? 0u : 16384u) + off, src);
        }
    };

    float acc[4][4][4];
    #pragma unroll
    for (int mt = 0; mt < 4; mt++)
        #pragma unroll
        for (int nt = 0; nt < 4; nt++)
            #pragma unroll
            for (int r = 0; r < 4; r++) acc[mt][nt][r] = 0.f;

    uint32_t a_row = (uint32_t)(warp_m * 64 + (lane & 15));
    uint32_t a_kb  = (uint32_t)((lane >> 4) << 4);
    uint32_t b_row = (uint32_t)(warp_n * 32 + (lane & 15));

    load_tile(0, 0); CP_COMMIT();

    for (int kt = 0; kt < 48; kt++) {
        int cur = kt & 1;
        if (kt + 1 < 48) { load_tile(kt + 1, cur ^ 1); CP_COMMIT(); CP_WAIT(1); }
        else             { CP_WAIT(0); }
        __syncthreads();

        uint32_t abase = sm + cur * STAGE_BYTES;
        uint32_t bbase = abase + 16384u;
        #pragma unroll
        for (int ks = 0; ks < 4; ks++) {
            uint32_t kb = (uint32_t)(ks * 32);
            uint32_t af[4][4], bw[2][4];
            #pragma unroll
            for (int mt = 0; mt < 4; mt++)
                ldsm4(af[mt], abase + sw128((a_row + mt * 16) * 128 + kb + a_kb));
            #pragma unroll
            for (int p = 0; p < 2; p++)
                ldsm4(bw[p], bbase + sw128((b_row + p * 16) * 128 + kb + a_kb));
            #pragma unroll
            for (int mt = 0; mt < 4; mt++)
                #pragma unroll
                for (int p = 0; p < 2; p++) {
                    mma16816v(acc[mt][2 * p],     af[mt], bw[p][0], bw[p][2]);
                    mma16816v(acc[mt][2 * p + 1], af[mt], bw[p][1], bw[p][3]);
                }
        }
        __syncthreads();
    }

    // ---- epilogue: bias (+0.125 scale for Q) -> bf16 hi/lo splits ----
    int gq = lane >> 2;
    float scale = (z == 0) ? 0.125f : 1.0f;
    #pragma unroll
    for (int mt = 0; mt < 4; mt++) {
        int m_lo = m0 + warp_m * 64 + mt * 16 + gq;
        #pragma unroll
        for (int half = 0; half < 2; half++) {
            int m = m_lo + half * 8;
            int b = m >> 10, s = m & 1023;
            #pragma unroll
            for (int nt = 0; nt < 4; nt++) {
                int nc = warp_n * 32 + nt * 8 + (lane & 3) * 2;
                int n = n0 + nc;
                int h = n >> 6, dh = n & 63;
                int bh = b * NH + h;
                float c0 = (acc[mt][nt][half * 2 + 0] + biasS[nc]) * scale;
                float c1 = (acc[mt][nt][half * 2 + 1] + biasS[nc + 1]) * scale;
                __nv_bfloat162 hv = __floats2bfloat162_rn(c0, c1);
                __nv_bfloat162 lv = __floats2bfloat162_rn(c0 - __bfloat162float(hv.x),
                                                          c1 - __bfloat162float(hv.y));
                if (z == 2) {
                    size_t o = (((size_t)bh * 2 + 0) * NS + s) * NDH + dh;
                    *(__nv_bfloat162*)&g_Vs[o] = hv;
                    *(__nv_bfloat162*)&g_Vs[o + (size_t)NS * NDH] = lv;
                } else {
                    __nv_bfloat16* dst = (z == 0) ? g_Qs : g_Ks;
                    size_t o = (((size_t)bh * 3 + 0) * NS + s) * NDH + dh;
                    size_t seg = (size_t)NS * NDH;
                    if (z == 0) {   // [qh|qh|ql]
                        *(__nv_bfloat162*)&dst[o]           = hv;
                        *(__nv_bfloat162*)&dst[o + seg]     = hv;
                        *(__nv_bfloat162*)&dst[o + 2 * seg] = lv;
                    } else {        // [kh|kl|kh]
                        *(__nv_bfloat162*)&dst[o]           = hv;
                        *(__nv_bfloat162*)&dst[o + seg]     = lv;
                        *(__nv_bfloat162*)&dst[o + 2 * seg] = hv;
                    }
                }
            }
        }
    }
}

// ============================================================================
// Attention via mma.sync (round-5 proven version). CTA: 64 q x one (b,h).
// 8 k-tiles of 128, double-buffered. QK: M64 N128 K192. AV: 3 split terms.
// ============================================================================
#define QS_OFF 0u
#define KS_OFF 24576u
#define VS_OFF 122880u
#define P_OFF  188416u
#define RS_OFF 221184u
#define ATT_SMEM 221440u

__global__ __launch_bounds__(256, 1)
void attn_mma_kernel(float* __restrict__ out_ctx, float* __restrict__ out_att)
{
    extern __shared__ char smraw[];
    uint32_t sm = smem_u32(smraw);
    float* rowsumS = (float*)(smraw + RS_OFF);

    int t = threadIdx.x;
    int wid = t >> 5, lane = t & 31;
    int warp_m = wid & 1, warp_n = wid >> 1;
    int bh = blockIdx.y;
    int q0 = blockIdx.x * 64;

    const __nv_bfloat16* Qg = g_Qs + ((size_t)bh * 3 * NS + q0) * NDH;
    const __nv_bfloat16* Kg = g_Ks + (size_t)bh * 3 * NS * NDH;
    const __nv_bfloat16* Vg = g_Vs + (size_t)bh * 2 * NS * NDH;

    #pragma unroll
    for (int i = 0; i < 6; i++) {
        int c = t + i * 256;
        int seg = c >> 9, row = (c >> 3) & 63, col = c & 7;
        cp_async16(sm + QS_OFF + seg * 8192u + sw128((uint32_t)(row * 128 + col * 16)),
                   Qg + ((size_t)seg * NS + row) * NDH + col * 8);
    }
    auto load_kv = [&](int kt, int buf) {
        #pragma unroll
        for (int i = 0; i < 12; i++) {
            int c = t + i * 256;
            int seg = c >> 10, row = (c >> 3) & 127, col = c & 7;
            cp_async16(sm + KS_OFF + buf * 49152u + seg * 16384u
                          + sw128((uint32_t)(row * 128 + col * 16)),
                       Kg + (((size_t)seg * NS) + kt * 128 + row) * NDH + col * 8);
        }
        #pragma unroll
        for (int i = 0; i < 8; i++) {
            int c = t + i * 256;
            int hl = c >> 10, row = (c >> 3) & 127, col = c & 7;
            cp_async16(sm + VS_OFF + buf * 32768u + hl * 16384u
                          + sw128((uint32_t)(row * 128 + col * 16)),
                       Vg + (((size_t)hl * NS) + kt * 128 + row) * NDH + col * 8);
        }
    };
    load_kv(0, 0); CP_COMMIT();
    if (t < 64) rowsumS[t] = 0.f;

    float ctx[2][2][4];
    #pragma unroll
    for (int mt = 0; mt < 2; mt++)
        #pragma unroll
        for (int nt = 0; nt < 2; nt++)
            #pragma unroll
            for (int r = 0; r < 4; r++) ctx[mt][nt][r] = 0.f;

    uint32_t a_row = (uint32_t)(warp_m * 32 + (lane & 15));
    uint32_t a_kb  = (uint32_t)((lane >> 4) << 4);
    uint32_t b_row = (uint32_t)(warp_n * 32 + (lane & 7));
    uint32_t b_kb  = (uint32_t)(((lane >> 3) & 1) << 4);

    for (int kt = 0; kt < 8; kt++) {
        int cur = kt & 1;
        CP_WAIT(0);
        __syncthreads();
        if (kt + 1 < 8) { load_kv(kt + 1, cur ^ 1); CP_COMMIT(); }

        float sacc[2][4][4];
        #pragma unroll
        for (int mt = 0; mt < 2; mt++)
            #pragma unroll
            for (int nt = 0; nt < 4; nt++)
                #pragma unroll
                for (int r = 0; r < 4; r++) sacc[mt][nt][r] = 0.f;

        uint32_t kbase = sm + KS_OFF + cur * 49152u;
        #pragma unroll
        for (int ks = 0; ks < 12; ks++) {
            uint32_t seg = (uint32_t)(ks >> 2), kb = (uint32_t)((ks & 3) * 32);
            uint32_t af[2][4], bf[4][2];
            #pragma unroll
            for (int mt = 0; mt < 2; mt++)
                ldsm4(af[mt], sm + QS_OFF + seg * 8192u
                              + sw128((a_row + mt * 16) * 128 + kb + a_kb));
            #pragma unroll
            for (int nt = 0; nt < 4; nt++)
                ldsm2(bf[nt], kbase + seg * 16384u
                              + sw128((b_row + nt * 8) * 128 + kb + b_kb));
            #pragma unroll
            for (int mt = 0; mt < 2; mt++)
                #pragma unroll
                for (int nt = 0; nt < 4; nt++)
                    mma16816(sacc[mt][nt], af[mt], bf[nt]);
        }

        size_t attbase = ((size_t)bh * NS + q0) * NS + (size_t)kt * 128;
        #pragma unroll
        for (int mt = 0; mt < 2; mt++) {
            float p0 = 0.f, p1 = 0.f;
            int r0 = warp_m * 32 + mt * 16 + (lane >> 2);
            #pragma unroll
            for (int nt = 0; nt < 4; nt++) {
                int kc = warp_n * 32 + nt * 8 + (lane & 3) * 2;
                float e0 = __expf(sacc[mt][nt][0]);
                float e1 = __expf(sacc[mt][nt][1]);
                float e2 = __expf(sacc[mt][nt][2]);
                float e3 = __expf(sacc[mt][nt][3]);
                p0 += e0 + e1; p1 += e2 + e3;
                *(float2*)&out_att[attbase + (size_t)r0 * NS + kc]       = make_float2(e0, e1);
                *(float2*)&out_att[attbase + (size_t)(r0 + 8) * NS + kc] = make_float2(e2, e3);
                __nv_bfloat162 h0 = __floats2bfloat162_rn(e0, e1);
                __nv_bfloat162 l0 = __floats2bfloat162_rn(e0 - __bfloat162float(h0.x),
                                                          e1 - __bfloat162float(h0.y));
                __nv_bfloat162 h1 = __floats2bfloat162_rn(e2, e3);
                __nv_bfloat162 l1 = __floats2bfloat162_rn(e2 - __bfloat162float(h1.x),
                                                          e3 - __bfloat162float(h1.y));
                uint32_t po = (uint32_t)((kc >> 6) * 8192) + sw128((uint32_t)(r0 * 128 + (kc & 63) * 2));
                uint32_t po8 = (uint32_t)((kc >> 6) * 8192) + sw128((uint32_t)((r0 + 8) * 128 + (kc & 63) * 2));
                *(__nv_bfloat162*)(smraw + P_OFF + po)            = h0;
                *(__nv_bfloat162*)(smraw + P_OFF + 16384u + po)   = l0;
                *(__nv_bfloat162*)(smraw + P_OFF + po8)           = h1;
                *(__nv_bfloat162*)(smraw + P_OFF + 16384u + po8)  = l1;
            }
            p0 += __shfl_xor_sync(0xffffffffu, p0, 1);
            p0 += __shfl_xor_sync(0xffffffffu, p0, 2);
            p1 += __shfl_xor_sync(0xffffffffu, p1, 1);
            p1 += __shfl_xor_sync(0xffffffffu, p1, 2);
            if ((lane & 3) == 0) {
                atomicAdd(&rowsumS[r0], p0);
                atomicAdd(&rowsumS[r0 + 8], p1);
            }
        }
        __syncthreads();

        uint32_t vbase = sm + VS_OFF + cur * 32768u;
        #pragma unroll
        for (int term = 0; term < 3; term++) {
            uint32_t pb = sm + P_OFF + (term == 2 ? 16384u : 0u);
            uint32_t vb = vbase + (term == 1 ? 16384u : 0u);
            #pragma unroll
            for (int ks = 0; ks < 8; ks++) {
                uint32_t kbyte = (uint32_t)(ks * 32) + a_kb;
                uint32_t af[2][4], bv[4];
                #pragma unroll
                for (int mt = 0; mt < 2; mt++)
                    ldsm4(af[mt], pb + (kbyte >> 7) * 8192u
                                  + sw128((a_row + mt * 16) * 128 + (kbyte & 127)));
                ldsm4t(bv, vb + sw128((uint32_t)((ks * 16 + (lane & 15)) * 128)
                                      + (uint32_t)(warp_n * 32) + (uint32_t)((lane >> 4) * 16)));
                #pragma unroll
                for (int mt = 0; mt < 2; mt++) {
                    mma16816(ctx[mt][0], af[mt], bv);
                    mma16816(ctx[mt][1], af[mt], bv + 2);
                }
            }
        }
        __syncthreads();
    }

    if (t < 64) g_rowsum[(size_t)bh * NS + q0 + t] = rowsumS[t];
    __syncthreads();

    int b = bh >> 4, h = bh & 15;
    #pragma unroll
    for (int mt = 0; mt < 2; mt++) {
        #pragma unroll
        for (int half = 0; half < 2; half++) {
            int r = warp_m * 32 + mt * 16 + (lane >> 2) + half * 8;
            float inv = 1.0f / rowsumS[r];
            size_t o = ((size_t)(b * NS + q0 + r)) * ND + h * NDH;
            #pragma unroll
            for (int nt = 0; nt < 2; nt++) {
                int d = warp_n * 16 + nt * 8 + (lane & 3) * 2;
                float c0 = ctx[mt][nt][half * 2 + 0] * inv;
                float c1 = ctx[mt][nt][half * 2 + 1] * inv;
                *(float2*)&out_ctx[o + d] = make_float2(c0, c1);
            }
        }
    }
}

// ============================================================================
// Normalize attention tensor by row sums (pure HBM pass).
// ============================================================================
__global__ __launch_bounds__(256) void norm_kernel(float* __restrict__ att)
{
    size_t i = ((size_t)blockIdx.x * 256 + threadIdx.x) * 4;
    float inv = 1.0f / __ldg(&g_rowsum[i >> 10]);
    float4 v = *(float4*)&att[i];
    v.x *= inv; v.y *= inv; v.z *= inv; v.w *= inv;
    *(float4*)&att[i] = v;
}

extern "C" void kernel_launch(void* const* d_in, const int* in_sizes, int n_in,
                              void* d_out, int out_size) {
    const float* x  = (const float*)d_in[0];
    const float* Wq = (const float*)d_in[1];
    const float* bq = (const float*)d_in[2];
    const float* Wk = (const float*)d_in[3];
    const float* bk = (const float*)d_in[4];
    const float* Wv = (const float*)d_in[5];
    const float* bv = (const float*)d_in[6];
    // d_in[7] structure_bias: constant along the softmax axis -> cancels exactly.

    float* out_ctx = (float*)d_out;
    float* out_att = out_ctx + (size_t)NB * NS * ND;

    cudaFuncSetAttribute(qkv_mma_kernel, cudaFuncAttributeMaxDynamicSharedMemorySize, QKV_SMEM);
    cudaFuncSetAttribute(attn_mma_kernel, cudaFuncAttributeMaxDynamicSharedMemorySize, ATT_SMEM);

    prep_x_kernel<<<8192, 256>>>(x);
    prep_w_kernel<<<dim3(1024, 3), 256>>>(Wq, Wk, Wv);
    qkv_mma_kernel<<<dim3(24, 64), 256, QKV_SMEM>>>(bq, bk, bv);
    attn_mma_kernel<<<dim3(16, 128), 256, ATT_SMEM>>>(out_ctx, out_att);
    norm_kernel<<<131072, 256>>>(out_att);
}